// round 7
// baseline (speedup 1.0000x reference)
#include <cuda_runtime.h>
#include <cuda_bf16.h>
#include <cstdint>

#define N_NODES 50000
#define N_EDGES 800000
#define F_IN    256
#define NH      4
#define HD      64

// ---------------- scratch (device globals; no allocs allowed) ----------------
__device__ float g_hsrc[N_NODES * HD];
__device__ float g_hdst[N_NODES * HD];
__device__ int   g_deg[N_NODES];
__device__ int   g_ptr[N_NODES];
__device__ int   g_cur[N_NODES];
__device__ int2  g_aedge[N_EDGES];        // CSR payload: (src, dst) per slot
__device__ float g_alpha[N_EDGES * NH];   // exp(score) per CSR slot, per head

// ---------------- CSR build ----------------
__global__ void init_deg_kernel() {
    int i = blockIdx.x * blockDim.x + threadIdx.x;
    if (i < N_NODES) g_deg[i] = 0;
}

__global__ void hist_kernel(const int* __restrict__ dst) {
    int base = (blockIdx.x * blockDim.x + threadIdx.x) * 4;
    if (base + 3 < N_EDGES) {
        int4 d = *(const int4*)(dst + base);
        atomicAdd(&g_deg[d.x], 1);
        atomicAdd(&g_deg[d.y], 1);
        atomicAdd(&g_deg[d.z], 1);
        atomicAdd(&g_deg[d.w], 1);
    } else {
        for (int e = base; e < N_EDGES; e++) atomicAdd(&g_deg[dst[e]], 1);
    }
}

#define SCAN_T 1024
#define SCAN_CHUNK 49
__global__ __launch_bounds__(SCAN_T) void scan_kernel() {
    __shared__ int sm[SCAN_T];
    int t = threadIdx.x;
    int lo = t * SCAN_CHUNK;
    int hi = lo + SCAN_CHUNK; if (hi > N_NODES) hi = N_NODES;
    int sum = 0;
    for (int i = lo; i < hi; i++) sum += g_deg[i];
    sm[t] = sum;
    __syncthreads();
    for (int off = 1; off < SCAN_T; off <<= 1) {
        int v = (t >= off) ? sm[t - off] : 0;
        __syncthreads();
        sm[t] += v;
        __syncthreads();
    }
    int run = (t > 0) ? sm[t - 1] : 0;
    for (int i = lo; i < hi; i++) {
        g_ptr[i] = run; g_cur[i] = run;
        run += g_deg[i];
    }
}

__global__ void scatter_kernel(const int* __restrict__ src, const int* __restrict__ dst) {
    int base = (blockIdx.x * blockDim.x + threadIdx.x) * 4;
    if (base + 3 < N_EDGES) {
        int4 d = *(const int4*)(dst + base);
        int4 s = *(const int4*)(src + base);
        int p0 = atomicAdd(&g_cur[d.x], 1);
        int p1 = atomicAdd(&g_cur[d.y], 1);
        int p2 = atomicAdd(&g_cur[d.z], 1);
        int p3 = atomicAdd(&g_cur[d.w], 1);
        g_aedge[p0] = make_int2(s.x, d.x);
        g_aedge[p1] = make_int2(s.y, d.y);
        g_aedge[p2] = make_int2(s.z, d.z);
        g_aedge[p3] = make_int2(s.w, d.w);
    } else {
        for (int e = base; e < N_EDGES; e++) {
            int pos = atomicAdd(&g_cur[dst[e]], 1);
            g_aedge[pos] = make_int2(src[e], dst[e]);
        }
    }
}

// ---------------- helpers ----------------
__device__ __forceinline__ uint32_t smem_u32(const void* p) {
    uint32_t a;
    asm("{ .reg .u64 t; cvta.to.shared.u64 t, %1; cvt.u32.u64 %0, t; }" : "=r"(a) : "l"(p));
    return a;
}
__device__ __forceinline__ void ldsm4(unsigned r[4], uint32_t a) {
    asm volatile("ldmatrix.sync.aligned.m8n8.x4.shared.b16 {%0,%1,%2,%3}, [%4];"
                 : "=r"(r[0]), "=r"(r[1]), "=r"(r[2]), "=r"(r[3]) : "r"(a));
}
__device__ __forceinline__ void mma_bf16(float c[4], const unsigned a[4], const unsigned b[2]) {
    asm volatile(
        "mma.sync.aligned.m16n8k16.row.col.f32.bf16.bf16.f32 "
        "{%0,%1,%2,%3}, {%4,%5,%6,%7}, {%8,%9}, {%0,%1,%2,%3};"
        : "+f"(c[0]), "+f"(c[1]), "+f"(c[2]), "+f"(c[3])
        : "r"(a[0]), "r"(a[1]), "r"(a[2]), "r"(a[3]), "r"(b[0]), "r"(b[1]));
}
__device__ __forceinline__ void cvt8(float4 a, float4 b, uint4& hi, uint4& lo) {
    float xs[8] = {a.x, a.y, a.z, a.w, b.x, b.y, b.z, b.w};
    unsigned h[4], l[4];
    #pragma unroll
    for (int i = 0; i < 4; i++) {
        float x = xs[2 * i], y = xs[2 * i + 1];
        __nv_bfloat16 hx = __float2bfloat16_rn(x);
        __nv_bfloat16 hy = __float2bfloat16_rn(y);
        __nv_bfloat16 lx = __float2bfloat16_rn(x - __bfloat162float(hx));
        __nv_bfloat16 ly = __float2bfloat16_rn(y - __bfloat162float(hy));
        unsigned short uhx = *(unsigned short*)&hx, uhy = *(unsigned short*)&hy;
        unsigned short ulx = *(unsigned short*)&lx, uly = *(unsigned short*)&ly;
        h[i] = (unsigned)uhx | ((unsigned)uhy << 16);
        l[i] = (unsigned)ulx | ((unsigned)uly << 16);
    }
    hi = make_uint4(h[0], h[1], h[2], h[3]);
    lo = make_uint4(l[0], l[1], l[2], l[3]);
}

// ---------------- HMMA bf16-split projection GEMM ----------------
#define RSB    144
#define SA_HI  0
#define SA_LO  18432
#define SB_HI  36864
#define SB_LO  55296
#define SM_TOT 73728

__global__ __launch_bounds__(256, 1)
void proj_mma_kernel(const float* __restrict__ feat,
                     const float* __restrict__ Wsrc, const float* __restrict__ bsrc,
                     const float* __restrict__ Wdst, const float* __restrict__ bdst)
{
    extern __shared__ char smem[];
    const uint32_t sb = smem_u32(smem);
    const int tid  = threadIdx.x;
    const int wid  = tid >> 5, lane = tid & 31;
    const int warp_m = wid & 3;
    const int warp_n = wid >> 2;
    const int m0 = blockIdx.x * 128;

    float acc[2][8][4];
    #pragma unroll
    for (int mt = 0; mt < 2; mt++)
        #pragma unroll
        for (int nt = 0; nt < 8; nt++)
            #pragma unroll
            for (int j = 0; j < 4; j++) acc[mt][nt][j] = 0.0f;

    float4 pa[4][2], pb[4][2];

    #define LOAD_A(c) do {                                                        \
        _Pragma("unroll")                                                         \
        for (int i = 0; i < 4; i++) {                                             \
            int t = tid + i * 256, row = t >> 3, seg = t & 7;                     \
            int node = m0 + row; if (node >= N_NODES) node = N_NODES - 1;         \
            const float* p = feat + (size_t)node * F_IN + (c) * 64 + seg * 8;     \
            pa[i][0] = *(const float4*)p; pa[i][1] = *(const float4*)(p + 4);     \
        } } while (0)

    #define LOAD_B(c) do {                                                        \
        _Pragma("unroll")                                                         \
        for (int i = 0; i < 4; i++) {                                             \
            int t = tid + i * 256, row = t >> 3, seg = t & 7;                     \
            const float* wr = (row < 64) ? (Wsrc + (size_t)row * F_IN)            \
                                         : (Wdst + (size_t)(row - 64) * F_IN);    \
            const float* p = wr + (c) * 64 + seg * 8;                             \
            pb[i][0] = *(const float4*)p; pb[i][1] = *(const float4*)(p + 4);     \
        } } while (0)

    #define STORE_AB() do {                                                       \
        _Pragma("unroll")                                                         \
        for (int i = 0; i < 4; i++) {                                             \
            int t = tid + i * 256, row = t >> 3, seg = t & 7;                     \
            uint32_t off = (uint32_t)(row * RSB + seg * 16);                      \
            uint4 hi, lo;                                                         \
            cvt8(pa[i][0], pa[i][1], hi, lo);                                     \
            *(uint4*)(smem + SA_HI + off) = hi;                                   \
            *(uint4*)(smem + SA_LO + off) = lo;                                   \
            cvt8(pb[i][0], pb[i][1], hi, lo);                                     \
            *(uint4*)(smem + SB_HI + off) = hi;                                   \
            *(uint4*)(smem + SB_LO + off) = lo;                                   \
        } } while (0)

    LOAD_A(0); LOAD_B(0);
    STORE_AB();
    __syncthreads();

    const uint32_t a_base = sb + SA_HI +
        (uint32_t)((warp_m * 32 + (lane & 15)) * RSB + (lane >> 4) * 16);
    const uint32_t b_base = sb + SB_HI +
        (uint32_t)((warp_n * 64 + (lane & 7) + ((lane >> 4) & 1) * 8) * RSB +
                   ((lane >> 3) & 1) * 16);

    for (int c = 0; c < 4; c++) {
        if (c < 3) { LOAD_A(c + 1); LOAD_B(c + 1); }

        #pragma unroll
        for (int ks = 0; ks < 4; ks++) {
            unsigned ah[2][4], al[2][4];
            #pragma unroll
            for (int mt = 0; mt < 2; mt++) {
                ldsm4(ah[mt], a_base + (uint32_t)(mt * 16 * RSB + ks * 32));
                ldsm4(al[mt], a_base + (uint32_t)(18432 + mt * 16 * RSB + ks * 32));
            }
            unsigned bh[4][4], bl[4][4];
            #pragma unroll
            for (int p = 0; p < 4; p++) {
                ldsm4(bh[p], b_base + (uint32_t)(p * 16 * RSB + ks * 32));
                ldsm4(bl[p], b_base + (uint32_t)(18432 + p * 16 * RSB + ks * 32));
            }
            #pragma unroll
            for (int mt = 0; mt < 2; mt++)
                #pragma unroll
                for (int nt = 0; nt < 8; nt++) {
                    const unsigned* bhf = &bh[nt >> 1][(nt & 1) * 2];
                    const unsigned* blf = &bl[nt >> 1][(nt & 1) * 2];
                    mma_bf16(acc[mt][nt], ah[mt], bhf);
                    mma_bf16(acc[mt][nt], ah[mt], blf);
                    mma_bf16(acc[mt][nt], al[mt], bhf);
                }
        }
        __syncthreads();
        if (c < 3) { STORE_AB(); __syncthreads(); }
    }

    #pragma unroll
    for (int mt = 0; mt < 2; mt++)
        #pragma unroll
        for (int nt = 0; nt < 8; nt++) {
            int row = warp_m * 32 + mt * 16 + (lane >> 2);
            int o   = warp_n * 64 + nt * 8 + (lane & 3) * 2;
            float* buf; int col;
            float b0, b1;
            if (o < 64) { col = o;      buf = g_hsrc; b0 = bsrc[col]; b1 = bsrc[col + 1]; }
            else        { col = o - 64; buf = g_hdst; b0 = bdst[col]; b1 = bdst[col + 1]; }
            int n0 = m0 + row, n1 = m0 + row + 8;
            if (n0 < N_NODES)
                *(float2*)(buf + (size_t)n0 * HD + col) =
                    make_float2(acc[mt][nt][0] + b0, acc[mt][nt][1] + b1);
            if (n1 < N_NODES)
                *(float2*)(buf + (size_t)n1 * HD + col) =
                    make_float2(acc[mt][nt][2] + b0, acc[mt][nt][3] + b1);
        }
}

// ---------------- score kernel: one thread per (CSR slot, head) ----------------
// alpha[pos][h] = exp(dot(leakyrelu(el + er), attn_h)). CSR order makes er
// gathers warp-local (same dst for consecutive slots).
__global__ __launch_bounds__(256) void score_kernel(const float* __restrict__ attn)
{
    int t = blockIdx.x * blockDim.x + threadIdx.x;
    if (t >= N_EDGES * NH) return;
    int pos = t >> 2, h = t & 3;
    int2 sd = g_aedge[pos];

    const float4* elp = (const float4*)(g_hsrc + (size_t)sd.x * HD + h * 16);
    const float4* erp = (const float4*)(g_hdst + (size_t)sd.y * HD + h * 16);
    const float4* ap  = (const float4*)(attn + h * 16);

    float acc = 0.0f;
    #pragma unroll
    for (int j = 0; j < 4; j++) {
        float4 a = elp[j], b = erp[j], w = ap[j];
        float v;
        v = a.x + b.x; v = (v > 0.f) ? v : 0.2f * v; acc += v * w.x;
        v = a.y + b.y; v = (v > 0.f) ? v : 0.2f * v; acc += v * w.y;
        v = a.z + b.z; v = (v > 0.f) ? v : 0.2f * v; acc += v * w.z;
        v = a.w + b.w; v = (v > 0.f) ? v : 0.2f * v; acc += v * w.w;
    }
    g_alpha[pos * NH + h] = __expf(acc);
}

// ---------------- aggregation: one warp per node; no shfl, no atomics ----------------
// lane owns dims {2*lane, 2*lane+1}; head = lane>>3. All inner-loop
// iterations independent -> MLP hides L2 gather latency.
__global__ __launch_bounds__(256) void agg_kernel(float* __restrict__ out)
{
    int warp = (blockIdx.x * blockDim.x + threadIdx.x) >> 5;
    int lane = threadIdx.x & 31;
    if (warp >= N_NODES) return;
    const int d = warp;
    const int h = lane >> 3;

    const int start = g_ptr[d];
    const int cnt   = g_deg[d];

    float2 acc = make_float2(0.f, 0.f);
    float  s   = 0.f;

    #pragma unroll 4
    for (int i = 0; i < cnt; i++) {
        int   sn = g_aedge[start + i].x;                       // uniform -> L1 broadcast
        float a  = g_alpha[(size_t)(start + i) * NH + h];      // uniform per 8 lanes
        float2 el = ((const float2*)(g_hsrc + (size_t)sn * HD))[lane];
        acc.x += a * el.x;
        acc.y += a * el.y;
        s     += a;
    }

    float inv = (s > 0.f) ? (1.f / s) : 0.f;
    ((float2*)(out + (size_t)d * HD))[lane] = make_float2(acc.x * inv, acc.y * inv);
}

extern "C" void kernel_launch(void* const* d_in, const int* in_sizes, int n_in,
                              void* d_out, int out_size)
{
    const float* feat = (const float*)d_in[0];
    const int*   src  = (const int*)d_in[1];
    const int*   dst  = (const int*)d_in[2];
    const float* Wsrc = (const float*)d_in[3];
    const float* bsrc = (const float*)d_in[4];
    const float* Wdst = (const float*)d_in[5];
    const float* bdst = (const float*)d_in[6];
    const float* attn = (const float*)d_in[7];
    float* out = (float*)d_out;

    cudaFuncSetAttribute(proj_mma_kernel, cudaFuncAttributeMaxDynamicSharedMemorySize, SM_TOT);

    // Fork: CSR build (src/dst only) || projection GEMM (feat/W only).
    cudaStream_t s2;
    cudaStreamCreateWithFlags(&s2, cudaStreamNonBlocking);
    cudaEvent_t evFork, evJoin;
    cudaEventCreateWithFlags(&evFork, cudaEventDisableTiming);
    cudaEventCreateWithFlags(&evJoin, cudaEventDisableTiming);

    cudaEventRecord(evFork, 0);
    cudaStreamWaitEvent(s2, evFork, 0);

    init_deg_kernel<<<(N_NODES + 255) / 256, 256, 0, s2>>>();
    hist_kernel<<<(N_EDGES / 4 + 255) / 256, 256, 0, s2>>>(dst);
    scan_kernel<<<1, SCAN_T, 0, s2>>>();
    scatter_kernel<<<(N_EDGES / 4 + 255) / 256, 256, 0, s2>>>(src, dst);
    cudaEventRecord(evJoin, s2);

    proj_mma_kernel<<<(N_NODES + 127) / 128, 256, SM_TOT>>>(feat, Wsrc, bsrc, Wdst, bdst);

    cudaStreamWaitEvent(0, evJoin, 0);
    score_kernel<<<(N_EDGES * NH + 255) / 256, 256>>>(attn);
    agg_kernel<<<(N_NODES * 32 + 255) / 256, 256>>>(out);
}

// round 8
// speedup vs baseline: 1.2190x; 1.2190x over previous
#include <cuda_runtime.h>
#include <cuda_bf16.h>
#include <cstdint>

#define N_NODES 50000
#define N_EDGES 800000
#define F_IN    256
#define NH      4
#define HD      64

// ---------------- scratch (device globals; no allocs allowed) ----------------
__device__ float g_hsrc[N_NODES * HD];
__device__ float g_hdst[N_NODES * HD];
__device__ int   g_deg[N_NODES];
__device__ int   g_ptr[N_NODES];
__device__ int   g_cur[N_NODES];
__device__ int   g_asrc[N_EDGES];

// ---------------- CSR build ----------------
__global__ void init_deg_kernel() {
    int i = blockIdx.x * blockDim.x + threadIdx.x;
    if (i < N_NODES) g_deg[i] = 0;
}

__global__ void hist_kernel(const int* __restrict__ dst) {
    int base = (blockIdx.x * blockDim.x + threadIdx.x) * 4;
    if (base + 3 < N_EDGES) {
        int4 d = *(const int4*)(dst + base);
        atomicAdd(&g_deg[d.x], 1);
        atomicAdd(&g_deg[d.y], 1);
        atomicAdd(&g_deg[d.z], 1);
        atomicAdd(&g_deg[d.w], 1);
    } else {
        for (int e = base; e < N_EDGES; e++) atomicAdd(&g_deg[dst[e]], 1);
    }
}

#define SCAN_T 1024
#define SCAN_CHUNK 49
__global__ __launch_bounds__(SCAN_T) void scan_kernel() {
    __shared__ int sm[SCAN_T];
    int t = threadIdx.x;
    int lo = t * SCAN_CHUNK;
    int hi = lo + SCAN_CHUNK; if (hi > N_NODES) hi = N_NODES;
    int sum = 0;
    for (int i = lo; i < hi; i++) sum += g_deg[i];
    sm[t] = sum;
    __syncthreads();
    for (int off = 1; off < SCAN_T; off <<= 1) {
        int v = (t >= off) ? sm[t - off] : 0;
        __syncthreads();
        sm[t] += v;
        __syncthreads();
    }
    int run = (t > 0) ? sm[t - 1] : 0;
    for (int i = lo; i < hi; i++) {
        g_ptr[i] = run; g_cur[i] = run;
        run += g_deg[i];
    }
}

__global__ void scatter_kernel(const int* __restrict__ src, const int* __restrict__ dst) {
    int base = (blockIdx.x * blockDim.x + threadIdx.x) * 4;
    if (base + 3 < N_EDGES) {
        int4 d = *(const int4*)(dst + base);
        int4 s = *(const int4*)(src + base);
        int p0 = atomicAdd(&g_cur[d.x], 1);
        int p1 = atomicAdd(&g_cur[d.y], 1);
        int p2 = atomicAdd(&g_cur[d.z], 1);
        int p3 = atomicAdd(&g_cur[d.w], 1);
        g_asrc[p0] = s.x; g_asrc[p1] = s.y; g_asrc[p2] = s.z; g_asrc[p3] = s.w;
    } else {
        for (int e = base; e < N_EDGES; e++) {
            int pos = atomicAdd(&g_cur[dst[e]], 1);
            g_asrc[pos] = src[e];
        }
    }
}

// ---------------- helpers ----------------
__device__ __forceinline__ uint32_t smem_u32(const void* p) {
    uint32_t a;
    asm("{ .reg .u64 t; cvta.to.shared.u64 t, %1; cvt.u32.u64 %0, t; }" : "=r"(a) : "l"(p));
    return a;
}
__device__ __forceinline__ void ldsm4(unsigned r[4], uint32_t a) {
    asm volatile("ldmatrix.sync.aligned.m8n8.x4.shared.b16 {%0,%1,%2,%3}, [%4];"
                 : "=r"(r[0]), "=r"(r[1]), "=r"(r[2]), "=r"(r[3]) : "r"(a));
}
__device__ __forceinline__ void mma_bf16(float c[4], const unsigned a[4], const unsigned b[2]) {
    asm volatile(
        "mma.sync.aligned.m16n8k16.row.col.f32.bf16.bf16.f32 "
        "{%0,%1,%2,%3}, {%4,%5,%6,%7}, {%8,%9}, {%0,%1,%2,%3};"
        : "+f"(c[0]), "+f"(c[1]), "+f"(c[2]), "+f"(c[3])
        : "r"(a[0]), "r"(a[1]), "r"(a[2]), "r"(a[3]), "r"(b[0]), "r"(b[1]));
}
__device__ __forceinline__ void cvt8(float4 a, float4 b, uint4& hi, uint4& lo) {
    float xs[8] = {a.x, a.y, a.z, a.w, b.x, b.y, b.z, b.w};
    unsigned h[4], l[4];
    #pragma unroll
    for (int i = 0; i < 4; i++) {
        float x = xs[2 * i], y = xs[2 * i + 1];
        __nv_bfloat16 hx = __float2bfloat16_rn(x);
        __nv_bfloat16 hy = __float2bfloat16_rn(y);
        __nv_bfloat16 lx = __float2bfloat16_rn(x - __bfloat162float(hx));
        __nv_bfloat16 ly = __float2bfloat16_rn(y - __bfloat162float(hy));
        unsigned short uhx = *(unsigned short*)&hx, uhy = *(unsigned short*)&hy;
        unsigned short ulx = *(unsigned short*)&lx, uly = *(unsigned short*)&ly;
        h[i] = (unsigned)uhx | ((unsigned)uhy << 16);
        l[i] = (unsigned)ulx | ((unsigned)uly << 16);
    }
    hi = make_uint4(h[0], h[1], h[2], h[3]);
    lo = make_uint4(l[0], l[1], l[2], l[3]);
}

// ---------------- HMMA bf16-split projection GEMM ----------------
#define RSB    144
#define SA_HI  0
#define SA_LO  18432
#define SB_HI  36864
#define SB_LO  55296
#define SM_TOT 73728

__global__ __launch_bounds__(256, 1)
void proj_mma_kernel(const float* __restrict__ feat,
                     const float* __restrict__ Wsrc, const float* __restrict__ bsrc,
                     const float* __restrict__ Wdst, const float* __restrict__ bdst)
{
    extern __shared__ char smem[];
    const uint32_t sb = smem_u32(smem);
    const int tid  = threadIdx.x;
    const int wid  = tid >> 5, lane = tid & 31;
    const int warp_m = wid & 3;
    const int warp_n = wid >> 2;
    const int m0 = blockIdx.x * 128;

    float acc[2][8][4];
    #pragma unroll
    for (int mt = 0; mt < 2; mt++)
        #pragma unroll
        for (int nt = 0; nt < 8; nt++)
            #pragma unroll
            for (int j = 0; j < 4; j++) acc[mt][nt][j] = 0.0f;

    float4 pa[4][2], pb[4][2];

    #define LOAD_A(c) do {                                                        \
        _Pragma("unroll")                                                         \
        for (int i = 0; i < 4; i++) {                                             \
            int t = tid + i * 256, row = t >> 3, seg = t & 7;                     \
            int node = m0 + row; if (node >= N_NODES) node = N_NODES - 1;         \
            const float* p = feat + (size_t)node * F_IN + (c) * 64 + seg * 8;     \
            pa[i][0] = *(const float4*)p; pa[i][1] = *(const float4*)(p + 4);     \
        } } while (0)

    #define LOAD_B(c) do {                                                        \
        _Pragma("unroll")                                                         \
        for (int i = 0; i < 4; i++) {                                             \
            int t = tid + i * 256, row = t >> 3, seg = t & 7;                     \
            const float* wr = (row < 64) ? (Wsrc + (size_t)row * F_IN)            \
                                         : (Wdst + (size_t)(row - 64) * F_IN);    \
            const float* p = wr + (c) * 64 + seg * 8;                             \
            pb[i][0] = *(const float4*)p; pb[i][1] = *(const float4*)(p + 4);     \
        } } while (0)

    #define STORE_AB() do {                                                       \
        _Pragma("unroll")                                                         \
        for (int i = 0; i < 4; i++) {                                             \
            int t = tid + i * 256, row = t >> 3, seg = t & 7;                     \
            uint32_t off = (uint32_t)(row * RSB + seg * 16);                      \
            uint4 hi, lo;                                                         \
            cvt8(pa[i][0], pa[i][1], hi, lo);                                     \
            *(uint4*)(smem + SA_HI + off) = hi;                                   \
            *(uint4*)(smem + SA_LO + off) = lo;                                   \
            cvt8(pb[i][0], pb[i][1], hi, lo);                                     \
            *(uint4*)(smem + SB_HI + off) = hi;                                   \
            *(uint4*)(smem + SB_LO + off) = lo;                                   \
        } } while (0)

    LOAD_A(0); LOAD_B(0);
    STORE_AB();
    __syncthreads();

    const uint32_t a_base = sb + SA_HI +
        (uint32_t)((warp_m * 32 + (lane & 15)) * RSB + (lane >> 4) * 16);
    const uint32_t b_base = sb + SB_HI +
        (uint32_t)((warp_n * 64 + (lane & 7) + ((lane >> 4) & 1) * 8) * RSB +
                   ((lane >> 3) & 1) * 16);

    for (int c = 0; c < 4; c++) {
        if (c < 3) { LOAD_A(c + 1); LOAD_B(c + 1); }

        #pragma unroll
        for (int ks = 0; ks < 4; ks++) {
            unsigned ah[2][4], al[2][4];
            #pragma unroll
            for (int mt = 0; mt < 2; mt++) {
                ldsm4(ah[mt], a_base + (uint32_t)(mt * 16 * RSB + ks * 32));
                ldsm4(al[mt], a_base + (uint32_t)(18432 + mt * 16 * RSB + ks * 32));
            }
            unsigned bh[4][4], bl[4][4];
            #pragma unroll
            for (int p = 0; p < 4; p++) {
                ldsm4(bh[p], b_base + (uint32_t)(p * 16 * RSB + ks * 32));
                ldsm4(bl[p], b_base + (uint32_t)(18432 + p * 16 * RSB + ks * 32));
            }
            #pragma unroll
            for (int mt = 0; mt < 2; mt++)
                #pragma unroll
                for (int nt = 0; nt < 8; nt++) {
                    const unsigned* bhf = &bh[nt >> 1][(nt & 1) * 2];
                    const unsigned* blf = &bl[nt >> 1][(nt & 1) * 2];
                    mma_bf16(acc[mt][nt], ah[mt], bhf);
                    mma_bf16(acc[mt][nt], ah[mt], blf);
                    mma_bf16(acc[mt][nt], al[mt], bhf);
                }
        }
        __syncthreads();
        if (c < 3) { STORE_AB(); __syncthreads(); }
    }

    #pragma unroll
    for (int mt = 0; mt < 2; mt++)
        #pragma unroll
        for (int nt = 0; nt < 8; nt++) {
            int row = warp_m * 32 + mt * 16 + (lane >> 2);
            int o   = warp_n * 64 + nt * 8 + (lane & 3) * 2;
            float* buf; int col;
            float b0, b1;
            if (o < 64) { col = o;      buf = g_hsrc; b0 = bsrc[col]; b1 = bsrc[col + 1]; }
            else        { col = o - 64; buf = g_hdst; b0 = bdst[col]; b1 = bdst[col + 1]; }
            int n0 = m0 + row, n1 = m0 + row + 8;
            if (n0 < N_NODES)
                *(float2*)(buf + (size_t)n0 * HD + col) =
                    make_float2(acc[mt][nt][0] + b0, acc[mt][nt][1] + b1);
            if (n1 < N_NODES)
                *(float2*)(buf + (size_t)n1 * HD + col) =
                    make_float2(acc[mt][nt][2] + b0, acc[mt][nt][3] + b1);
        }
}

// ---------------- aggregation: one warp per node; 4 edges in flight ----------------
// lane owns dims {2*lane, 2*lane+1}; head = lane>>3. The 4 edges' gathers and
// xor-reduction chains are independent -> latency amortized 4x.
__global__ __launch_bounds__(256) void agg_kernel(float* __restrict__ out,
                                                  const float* __restrict__ attn)
{
    int warp = (blockIdx.x * blockDim.x + threadIdx.x) >> 5;
    int lane = threadIdx.x & 31;
    if (warp >= N_NODES) return;
    const int d = warp;

    float2 er = ((const float2*)(g_hdst + (size_t)d * HD))[lane];
    float2 aw = ((const float2*)attn)[lane];

    const int start = g_ptr[d];
    const int cnt   = g_deg[d];

    float2 acc = make_float2(0.f, 0.f);
    float  s   = 0.f;

    for (int base = 0; base < cnt; base += 32) {
        int m = cnt - base; if (m > 32) m = 32;
        int sn_l = (lane < m) ? g_asrc[start + base + lane] : 0;

        int i = 0;
        for (; i + 4 <= m; i += 4) {
            // broadcast 4 src ids (independent)
            int sn0 = __shfl_sync(0xFFFFFFFFu, sn_l, i);
            int sn1 = __shfl_sync(0xFFFFFFFFu, sn_l, i + 1);
            int sn2 = __shfl_sync(0xFFFFFFFFu, sn_l, i + 2);
            int sn3 = __shfl_sync(0xFFFFFFFFu, sn_l, i + 3);
            // 4 independent gathers (MLP=4)
            float2 el0 = ((const float2*)(g_hsrc + (size_t)sn0 * HD))[lane];
            float2 el1 = ((const float2*)(g_hsrc + (size_t)sn1 * HD))[lane];
            float2 el2 = ((const float2*)(g_hsrc + (size_t)sn2 * HD))[lane];
            float2 el3 = ((const float2*)(g_hsrc + (size_t)sn3 * HD))[lane];
            // 4 partial dots
            float p0, p1, p2, p3, vx, vy;
            vx = el0.x + er.x; vx = (vx > 0.f) ? vx : 0.2f * vx;
            vy = el0.y + er.y; vy = (vy > 0.f) ? vy : 0.2f * vy;
            p0 = vx * aw.x + vy * aw.y;
            vx = el1.x + er.x; vx = (vx > 0.f) ? vx : 0.2f * vx;
            vy = el1.y + er.y; vy = (vy > 0.f) ? vy : 0.2f * vy;
            p1 = vx * aw.x + vy * aw.y;
            vx = el2.x + er.x; vx = (vx > 0.f) ? vx : 0.2f * vx;
            vy = el2.y + er.y; vy = (vy > 0.f) ? vy : 0.2f * vy;
            p2 = vx * aw.x + vy * aw.y;
            vx = el3.x + er.x; vx = (vx > 0.f) ? vx : 0.2f * vx;
            vy = el3.y + er.y; vy = (vy > 0.f) ? vy : 0.2f * vy;
            p3 = vx * aw.x + vy * aw.y;
            // interleaved xor reductions (independent chains)
            p0 += __shfl_xor_sync(0xFFFFFFFFu, p0, 1);
            p1 += __shfl_xor_sync(0xFFFFFFFFu, p1, 1);
            p2 += __shfl_xor_sync(0xFFFFFFFFu, p2, 1);
            p3 += __shfl_xor_sync(0xFFFFFFFFu, p3, 1);
            p0 += __shfl_xor_sync(0xFFFFFFFFu, p0, 2);
            p1 += __shfl_xor_sync(0xFFFFFFFFu, p1, 2);
            p2 += __shfl_xor_sync(0xFFFFFFFFu, p2, 2);
            p3 += __shfl_xor_sync(0xFFFFFFFFu, p3, 2);
            p0 += __shfl_xor_sync(0xFFFFFFFFu, p0, 4);
            p1 += __shfl_xor_sync(0xFFFFFFFFu, p1, 4);
            p2 += __shfl_xor_sync(0xFFFFFFFFu, p2, 4);
            p3 += __shfl_xor_sync(0xFFFFFFFFu, p3, 4);
            float a0 = __expf(p0), a1 = __expf(p1), a2 = __expf(p2), a3 = __expf(p3);
            acc.x += a0 * el0.x + a1 * el1.x + a2 * el2.x + a3 * el3.x;
            acc.y += a0 * el0.y + a1 * el1.y + a2 * el2.y + a3 * el3.y;
            s     += a0 + a1 + a2 + a3;
        }
        for (; i < m; i++) {
            int sn = __shfl_sync(0xFFFFFFFFu, sn_l, i);
            float2 el = ((const float2*)(g_hsrc + (size_t)sn * HD))[lane];
            float vx = el.x + er.x; vx = (vx > 0.f) ? vx : 0.2f * vx;
            float vy = el.y + er.y; vy = (vy > 0.f) ? vy : 0.2f * vy;
            float p  = vx * aw.x + vy * aw.y;
            p += __shfl_xor_sync(0xFFFFFFFFu, p, 1);
            p += __shfl_xor_sync(0xFFFFFFFFu, p, 2);
            p += __shfl_xor_sync(0xFFFFFFFFu, p, 4);
            float a = __expf(p);
            acc.x += a * el.x;
            acc.y += a * el.y;
            s     += a;
        }
    }

    float inv = (s > 0.f) ? (1.f / s) : 0.f;
    ((float2*)(out + (size_t)d * HD))[lane] = make_float2(acc.x * inv, acc.y * inv);
}

extern "C" void kernel_launch(void* const* d_in, const int* in_sizes, int n_in,
                              void* d_out, int out_size)
{
    const float* feat = (const float*)d_in[0];
    const int*   src  = (const int*)d_in[1];
    const int*   dst  = (const int*)d_in[2];
    const float* Wsrc = (const float*)d_in[3];
    const float* bsrc = (const float*)d_in[4];
    const float* Wdst = (const float*)d_in[5];
    const float* bdst = (const float*)d_in[6];
    const float* attn = (const float*)d_in[7];
    float* out = (float*)d_out;

    cudaFuncSetAttribute(proj_mma_kernel, cudaFuncAttributeMaxDynamicSharedMemorySize, SM_TOT);

    // Fork: CSR build (src/dst only) || projection GEMM (feat/W only).
    cudaStream_t s2;
    cudaStreamCreateWithFlags(&s2, cudaStreamNonBlocking);
    cudaEvent_t evFork, evJoin;
    cudaEventCreateWithFlags(&evFork, cudaEventDisableTiming);
    cudaEventCreateWithFlags(&evJoin, cudaEventDisableTiming);

    cudaEventRecord(evFork, 0);
    cudaStreamWaitEvent(s2, evFork, 0);

    init_deg_kernel<<<(N_NODES + 255) / 256, 256, 0, s2>>>();
    hist_kernel<<<(N_EDGES / 4 + 255) / 256, 256, 0, s2>>>(dst);
    scan_kernel<<<1, SCAN_T, 0, s2>>>();
    scatter_kernel<<<(N_EDGES / 4 + 255) / 256, 256, 0, s2>>>(src, dst);
    cudaEventRecord(evJoin, s2);

    proj_mma_kernel<<<(N_NODES + 127) / 128, 256, SM_TOT>>>(feat, Wsrc, bsrc, Wdst, bdst);

    cudaStreamWaitEvent(0, evJoin, 0);
    agg_kernel<<<(N_NODES * 32 + 255) / 256, 256>>>(out, attn);
}

// round 9
// speedup vs baseline: 1.2484x; 1.0241x over previous
#include <cuda_runtime.h>
#include <cuda_bf16.h>
#include <cstdint>

#define N_NODES 50000
#define N_EDGES 800000
#define F_IN    256
#define NH      4
#define HD      64

// ---------------- scratch (device globals; no allocs allowed) ----------------
__device__ float g_hsrc[N_NODES * HD];
__device__ float g_hdst[N_NODES * HD];
__device__ int   g_deg[N_NODES];
__device__ int   g_ptr[N_NODES];
__device__ int   g_cur[N_NODES];
__device__ int   g_asrc[N_EDGES];

// ---------------- CSR build ----------------
__global__ void init_deg_kernel() {
    int i = blockIdx.x * blockDim.x + threadIdx.x;
    if (i < N_NODES) g_deg[i] = 0;
}

__global__ void hist_kernel(const int* __restrict__ dst) {
    int base = (blockIdx.x * blockDim.x + threadIdx.x) * 4;
    if (base + 3 < N_EDGES) {
        int4 d = *(const int4*)(dst + base);
        atomicAdd(&g_deg[d.x], 1);
        atomicAdd(&g_deg[d.y], 1);
        atomicAdd(&g_deg[d.z], 1);
        atomicAdd(&g_deg[d.w], 1);
    } else {
        for (int e = base; e < N_EDGES; e++) atomicAdd(&g_deg[dst[e]], 1);
    }
}

#define SCAN_T 1024
#define SCAN_CHUNK 49
__global__ __launch_bounds__(SCAN_T) void scan_kernel() {
    __shared__ int sm[SCAN_T];
    int t = threadIdx.x;
    int lo = t * SCAN_CHUNK;
    int hi = lo + SCAN_CHUNK; if (hi > N_NODES) hi = N_NODES;
    int sum = 0;
    for (int i = lo; i < hi; i++) sum += g_deg[i];
    sm[t] = sum;
    __syncthreads();
    for (int off = 1; off < SCAN_T; off <<= 1) {
        int v = (t >= off) ? sm[t - off] : 0;
        __syncthreads();
        sm[t] += v;
        __syncthreads();
    }
    int run = (t > 0) ? sm[t - 1] : 0;
    for (int i = lo; i < hi; i++) {
        g_ptr[i] = run; g_cur[i] = run;
        run += g_deg[i];
    }
}

__global__ void scatter_kernel(const int* __restrict__ src, const int* __restrict__ dst) {
    int base = (blockIdx.x * blockDim.x + threadIdx.x) * 4;
    if (base + 3 < N_EDGES) {
        int4 d = *(const int4*)(dst + base);
        int4 s = *(const int4*)(src + base);
        int p0 = atomicAdd(&g_cur[d.x], 1);
        int p1 = atomicAdd(&g_cur[d.y], 1);
        int p2 = atomicAdd(&g_cur[d.z], 1);
        int p3 = atomicAdd(&g_cur[d.w], 1);
        g_asrc[p0] = s.x; g_asrc[p1] = s.y; g_asrc[p2] = s.z; g_asrc[p3] = s.w;
    } else {
        for (int e = base; e < N_EDGES; e++) {
            int pos = atomicAdd(&g_cur[dst[e]], 1);
            g_asrc[pos] = src[e];
        }
    }
}

// ---------------- helpers ----------------
__device__ __forceinline__ uint32_t smem_u32(const void* p) {
    uint32_t a;
    asm("{ .reg .u64 t; cvta.to.shared.u64 t, %1; cvt.u32.u64 %0, t; }" : "=r"(a) : "l"(p));
    return a;
}
__device__ __forceinline__ void ldsm4(unsigned r[4], uint32_t a) {
    asm volatile("ldmatrix.sync.aligned.m8n8.x4.shared.b16 {%0,%1,%2,%3}, [%4];"
                 : "=r"(r[0]), "=r"(r[1]), "=r"(r[2]), "=r"(r[3]) : "r"(a));
}
__device__ __forceinline__ void mma_bf16(float c[4], const unsigned a[4], const unsigned b[2]) {
    asm volatile(
        "mma.sync.aligned.m16n8k16.row.col.f32.bf16.bf16.f32 "
        "{%0,%1,%2,%3}, {%4,%5,%6,%7}, {%8,%9}, {%0,%1,%2,%3};"
        : "+f"(c[0]), "+f"(c[1]), "+f"(c[2]), "+f"(c[3])
        : "r"(a[0]), "r"(a[1]), "r"(a[2]), "r"(a[3]), "r"(b[0]), "r"(b[1]));
}
__device__ __forceinline__ void cvt8(float4 a, float4 b, uint4& hi, uint4& lo) {
    float xs[8] = {a.x, a.y, a.z, a.w, b.x, b.y, b.z, b.w};
    unsigned h[4], l[4];
    #pragma unroll
    for (int i = 0; i < 4; i++) {
        float x = xs[2 * i], y = xs[2 * i + 1];
        __nv_bfloat16 hx = __float2bfloat16_rn(x);
        __nv_bfloat16 hy = __float2bfloat16_rn(y);
        __nv_bfloat16 lx = __float2bfloat16_rn(x - __bfloat162float(hx));
        __nv_bfloat16 ly = __float2bfloat16_rn(y - __bfloat162float(hy));
        unsigned short uhx = *(unsigned short*)&hx, uhy = *(unsigned short*)&hy;
        unsigned short ulx = *(unsigned short*)&lx, uly = *(unsigned short*)&ly;
        h[i] = (unsigned)uhx | ((unsigned)uhy << 16);
        l[i] = (unsigned)ulx | ((unsigned)uly << 16);
    }
    hi = make_uint4(h[0], h[1], h[2], h[3]);
    lo = make_uint4(l[0], l[1], l[2], l[3]);
}

// ---------------- HMMA bf16-split projection GEMM v2 ----------------
// KC=32, double-buffered smem stages -> 2 CTAs/SM, 1 sync per chunk.
// Stage layout (per stage, 40960 B): Ahi +0, Alo +10240, Bhi +20480, Blo +30720.
// Row stride 80 B (32 bf16 + 16 pad) keeps ldmatrix conflict-free.
#define RSB2   80
#define TILE2  10240
#define STG2   40960
#define SM_TOT 81920

__global__ __launch_bounds__(256, 2)
void proj_mma_kernel(const float* __restrict__ feat,
                     const float* __restrict__ Wsrc, const float* __restrict__ bsrc,
                     const float* __restrict__ Wdst, const float* __restrict__ bdst)
{
    extern __shared__ char smem[];
    const uint32_t sb = smem_u32(smem);
    const int tid  = threadIdx.x;
    const int wid  = tid >> 5, lane = tid & 31;
    const int warp_m = wid & 3;
    const int warp_n = wid >> 2;
    const int m0 = blockIdx.x * 128;

    float acc[2][8][4];
    #pragma unroll
    for (int mt = 0; mt < 2; mt++)
        #pragma unroll
        for (int nt = 0; nt < 8; nt++)
            #pragma unroll
            for (int j = 0; j < 4; j++) acc[mt][nt][j] = 0.0f;

    // per chunk: A 128x32 fp32 + B 128x32 fp32; 512 tasks of 8 floats, 2/thread
    float4 pa[2][2], pb[2][2];

    #define LOAD_AB(c) do {                                                       \
        _Pragma("unroll")                                                         \
        for (int i = 0; i < 2; i++) {                                             \
            int t = tid + i * 256, row = t >> 2, seg = t & 3;                     \
            int node = m0 + row; if (node >= N_NODES) node = N_NODES - 1;         \
            const float* p = feat + (size_t)node * F_IN + (c) * 32 + seg * 8;     \
            pa[i][0] = *(const float4*)p; pa[i][1] = *(const float4*)(p + 4);     \
            const float* wr = (row < 64) ? (Wsrc + (size_t)row * F_IN)            \
                                         : (Wdst + (size_t)(row - 64) * F_IN);    \
            const float* q = wr + (c) * 32 + seg * 8;                             \
            pb[i][0] = *(const float4*)q; pb[i][1] = *(const float4*)(q + 4);     \
        } } while (0)

    #define STORE_AB(st) do {                                                     \
        _Pragma("unroll")                                                         \
        for (int i = 0; i < 2; i++) {                                             \
            int t = tid + i * 256, row = t >> 2, seg = t & 3;                     \
            uint32_t off = (uint32_t)((st) * STG2 + row * RSB2 + seg * 16);       \
            uint4 hi, lo;                                                         \
            cvt8(pa[i][0], pa[i][1], hi, lo);                                     \
            *(uint4*)(smem + off)         = hi;                                   \
            *(uint4*)(smem + TILE2 + off) = lo;                                   \
            cvt8(pb[i][0], pb[i][1], hi, lo);                                     \
            *(uint4*)(smem + 2 * TILE2 + off) = hi;                               \
            *(uint4*)(smem + 3 * TILE2 + off) = lo;                               \
        } } while (0)

    LOAD_AB(0);
    STORE_AB(0);
    __syncthreads();

    const uint32_t a_off = (uint32_t)((warp_m * 32 + (lane & 15)) * RSB2 + (lane >> 4) * 16);
    const uint32_t b_off = (uint32_t)((warp_n * 64 + (lane & 7) + ((lane >> 4) & 1) * 8) * RSB2 +
                                      ((lane >> 3) & 1) * 16);

    for (int c = 0; c < 8; c++) {
        const uint32_t st = (uint32_t)(c & 1) * STG2;
        if (c < 7) LOAD_AB(c + 1);   // global loads in flight during MMA

        #pragma unroll
        for (int ks = 0; ks < 2; ks++) {
            unsigned ah[2][4], al[2][4];
            #pragma unroll
            for (int mt = 0; mt < 2; mt++) {
                ldsm4(ah[mt], sb + st + a_off + (uint32_t)(mt * 16 * RSB2 + ks * 32));
                ldsm4(al[mt], sb + st + TILE2 + a_off + (uint32_t)(mt * 16 * RSB2 + ks * 32));
            }
            unsigned bh[4][4], bl[4][4];
            #pragma unroll
            for (int p = 0; p < 4; p++) {
                ldsm4(bh[p], sb + st + 2 * TILE2 + b_off + (uint32_t)(p * 16 * RSB2 + ks * 32));
                ldsm4(bl[p], sb + st + 3 * TILE2 + b_off + (uint32_t)(p * 16 * RSB2 + ks * 32));
            }
            #pragma unroll
            for (int mt = 0; mt < 2; mt++)
                #pragma unroll
                for (int nt = 0; nt < 8; nt++) {
                    const unsigned* bhf = &bh[nt >> 1][(nt & 1) * 2];
                    const unsigned* blf = &bl[nt >> 1][(nt & 1) * 2];
                    mma_bf16(acc[mt][nt], ah[mt], bhf);
                    mma_bf16(acc[mt][nt], ah[mt], blf);
                    mma_bf16(acc[mt][nt], al[mt], bhf);
                }
        }
        if (c < 7) STORE_AB((c + 1) & 1);   // writes other stage; safe pre-sync
        __syncthreads();
    }

    #pragma unroll
    for (int mt = 0; mt < 2; mt++)
        #pragma unroll
        for (int nt = 0; nt < 8; nt++) {
            int row = warp_m * 32 + mt * 16 + (lane >> 2);
            int o   = warp_n * 64 + nt * 8 + (lane & 3) * 2;
            float* buf; int col;
            float b0, b1;
            if (o < 64) { col = o;      buf = g_hsrc; b0 = bsrc[col]; b1 = bsrc[col + 1]; }
            else        { col = o - 64; buf = g_hdst; b0 = bdst[col]; b1 = bdst[col + 1]; }
            int n0 = m0 + row, n1 = m0 + row + 8;
            if (n0 < N_NODES)
                *(float2*)(buf + (size_t)n0 * HD + col) =
                    make_float2(acc[mt][nt][0] + b0, acc[mt][nt][1] + b1);
            if (n1 < N_NODES)
                *(float2*)(buf + (size_t)n1 * HD + col) =
                    make_float2(acc[mt][nt][2] + b0, acc[mt][nt][3] + b1);
        }
}

// ---------------- aggregation: one warp per node; 4 edges in flight ----------------
__global__ __launch_bounds__(256) void agg_kernel(float* __restrict__ out,
                                                  const float* __restrict__ attn)
{
    int warp = (blockIdx.x * blockDim.x + threadIdx.x) >> 5;
    int lane = threadIdx.x & 31;
    if (warp >= N_NODES) return;
    const int d = warp;

    float2 er = ((const float2*)(g_hdst + (size_t)d * HD))[lane];
    float2 aw = ((const float2*)attn)[lane];

    const int start = g_ptr[d];
    const int cnt   = g_deg[d];

    float2 acc = make_float2(0.f, 0.f);
    float  s   = 0.f;

    for (int base = 0; base < cnt; base += 32) {
        int m = cnt - base; if (m > 32) m = 32;
        int sn_l = (lane < m) ? g_asrc[start + base + lane] : 0;

        int i = 0;
        for (; i + 4 <= m; i += 4) {
            int sn0 = __shfl_sync(0xFFFFFFFFu, sn_l, i);
            int sn1 = __shfl_sync(0xFFFFFFFFu, sn_l, i + 1);
            int sn2 = __shfl_sync(0xFFFFFFFFu, sn_l, i + 2);
            int sn3 = __shfl_sync(0xFFFFFFFFu, sn_l, i + 3);
            float2 el0 = ((const float2*)(g_hsrc + (size_t)sn0 * HD))[lane];
            float2 el1 = ((const float2*)(g_hsrc + (size_t)sn1 * HD))[lane];
            float2 el2 = ((const float2*)(g_hsrc + (size_t)sn2 * HD))[lane];
            float2 el3 = ((const float2*)(g_hsrc + (size_t)sn3 * HD))[lane];
            float p0, p1, p2, p3, vx, vy;
            vx = el0.x + er.x; vx = (vx > 0.f) ? vx : 0.2f * vx;
            vy = el0.y + er.y; vy = (vy > 0.f) ? vy : 0.2f * vy;
            p0 = vx * aw.x + vy * aw.y;
            vx = el1.x + er.x; vx = (vx > 0.f) ? vx : 0.2f * vx;
            vy = el1.y + er.y; vy = (vy > 0.f) ? vy : 0.2f * vy;
            p1 = vx * aw.x + vy * aw.y;
            vx = el2.x + er.x; vx = (vx > 0.f) ? vx : 0.2f * vx;
            vy = el2.y + er.y; vy = (vy > 0.f) ? vy : 0.2f * vy;
            p2 = vx * aw.x + vy * aw.y;
            vx = el3.x + er.x; vx = (vx > 0.f) ? vx : 0.2f * vx;
            vy = el3.y + er.y; vy = (vy > 0.f) ? vy : 0.2f * vy;
            p3 = vx * aw.x + vy * aw.y;
            p0 += __shfl_xor_sync(0xFFFFFFFFu, p0, 1);
            p1 += __shfl_xor_sync(0xFFFFFFFFu, p1, 1);
            p2 += __shfl_xor_sync(0xFFFFFFFFu, p2, 1);
            p3 += __shfl_xor_sync(0xFFFFFFFFu, p3, 1);
            p0 += __shfl_xor_sync(0xFFFFFFFFu, p0, 2);
            p1 += __shfl_xor_sync(0xFFFFFFFFu, p1, 2);
            p2 += __shfl_xor_sync(0xFFFFFFFFu, p2, 2);
            p3 += __shfl_xor_sync(0xFFFFFFFFu, p3, 2);
            p0 += __shfl_xor_sync(0xFFFFFFFFu, p0, 4);
            p1 += __shfl_xor_sync(0xFFFFFFFFu, p1, 4);
            p2 += __shfl_xor_sync(0xFFFFFFFFu, p2, 4);
            p3 += __shfl_xor_sync(0xFFFFFFFFu, p3, 4);
            float a0 = __expf(p0), a1 = __expf(p1), a2 = __expf(p2), a3 = __expf(p3);
            acc.x += a0 * el0.x + a1 * el1.x + a2 * el2.x + a3 * el3.x;
            acc.y += a0 * el0.y + a1 * el1.y + a2 * el2.y + a3 * el3.y;
            s     += a0 + a1 + a2 + a3;
        }
        for (; i < m; i++) {
            int sn = __shfl_sync(0xFFFFFFFFu, sn_l, i);
            float2 el = ((const float2*)(g_hsrc + (size_t)sn * HD))[lane];
            float vx = el.x + er.x; vx = (vx > 0.f) ? vx : 0.2f * vx;
            float vy = el.y + er.y; vy = (vy > 0.f) ? vy : 0.2f * vy;
            float p  = vx * aw.x + vy * aw.y;
            p += __shfl_xor_sync(0xFFFFFFFFu, p, 1);
            p += __shfl_xor_sync(0xFFFFFFFFu, p, 2);
            p += __shfl_xor_sync(0xFFFFFFFFu, p, 4);
            float a = __expf(p);
            acc.x += a * el.x;
            acc.y += a * el.y;
            s     += a;
        }
    }

    float inv = (s > 0.f) ? (1.f / s) : 0.f;
    ((float2*)(out + (size_t)d * HD))[lane] = make_float2(acc.x * inv, acc.y * inv);
}

extern "C" void kernel_launch(void* const* d_in, const int* in_sizes, int n_in,
                              void* d_out, int out_size)
{
    const float* feat = (const float*)d_in[0];
    const int*   src  = (const int*)d_in[1];
    const int*   dst  = (const int*)d_in[2];
    const float* Wsrc = (const float*)d_in[3];
    const float* bsrc = (const float*)d_in[4];
    const float* Wdst = (const float*)d_in[5];
    const float* bdst = (const float*)d_in[6];
    const float* attn = (const float*)d_in[7];
    float* out = (float*)d_out;

    cudaFuncSetAttribute(proj_mma_kernel, cudaFuncAttributeMaxDynamicSharedMemorySize, SM_TOT);

    // Fork: CSR build (src/dst only) || projection GEMM (feat/W only).
    // proj submitted 4th so the ncu capture window lands on it.
    cudaStream_t s2;
    cudaStreamCreateWithFlags(&s2, cudaStreamNonBlocking);
    cudaEvent_t evFork, evJoin;
    cudaEventCreateWithFlags(&evFork, cudaEventDisableTiming);
    cudaEventCreateWithFlags(&evJoin, cudaEventDisableTiming);

    cudaEventRecord(evFork, 0);
    cudaStreamWaitEvent(s2, evFork, 0);

    init_deg_kernel<<<(N_NODES + 255) / 256, 256, 0, s2>>>();   // 1
    hist_kernel<<<(N_EDGES / 4 + 255) / 256, 256, 0, s2>>>(dst); // 2
    scan_kernel<<<1, SCAN_T, 0, s2>>>();                         // 3

    proj_mma_kernel<<<(N_NODES + 127) / 128, 256, SM_TOT>>>(feat, Wsrc, bsrc, Wdst, bdst); // 4

    scatter_kernel<<<(N_EDGES / 4 + 255) / 256, 256, 0, s2>>>(src, dst);                   // 5
    cudaEventRecord(evJoin, s2);

    cudaStreamWaitEvent(0, evJoin, 0);
    agg_kernel<<<(N_NODES * 32 + 255) / 256, 256>>>(out, attn);                            // 6
}